// round 13
// baseline (speedup 1.0000x reference)
#include <cuda_runtime.h>

#define BATCH 4
#define C1N 128
#define C2N 64
#define NPIX1 16384   // 128*128
#define NPIX2 65536   // 256*256
#define NB 256

// ---- scratch (device globals; zero-init at load; k_fuse re-zeroes g_gaps) ----
__device__ float g_gaps[BATCH * C1N + BATCH * C2N];  // [0,512): x1 sums, [512,768): x2 sums
__device__ __align__(16) float g_pos1[BATCH * NB * 64];   // [b][n][ij]
__device__ __align__(16) float g_pos2[BATCH * NB * 256];  // [b][n][ij]
__device__ __align__(16) float g_spa [BATCH * NPIX2];     // [b][h=n][w=k]
__device__ __align__(16) float g_w3t [BATCH * C2N * C2N]; // [b][c][o]  prefused, transposed
__device__ __align__(16) float g_s3  [C2N];
__device__ __align__(16) float g_t3  [C2N];

__device__ __forceinline__ float ex2f(float x) {   // guaranteed MUFU.EX2
    float r;
    asm("ex2.approx.ftz.f32 %0, %1;" : "=f"(r) : "f"(x));
    return r;
}

// ---- kernel 1: pos1 & pos2 + channel sums; NO in-loop reductions ----
__global__ void __launch_bounds__(256) k_pos(const float* __restrict__ x1,
                                             const float* __restrict__ wp1,
                                             const float* __restrict__ bp1,
                                             const float* __restrict__ x2,
                                             const float* __restrict__ wp2,
                                             const float* __restrict__ bp2) {
    __shared__ __align__(16) float part[8][256];
    __shared__ float cpart[8][16][33];   // padded: conflict-free column reads
    int tid = threadIdx.x, wid = tid >> 5, lane = tid & 31;

    if (blockIdx.x < 256) {
        // ---- pos1: warp owns 16 channels x 256 pixels ----
        int bid = blockIdx.x;
        int b = bid >> 6;
        int p0 = (bid & 63) << 8;
        const float* plane = x1 + (size_t)b * C1N * NPIX1 + p0;
        float d[8];
        #pragma unroll
        for (int k = 0; k < 8; k++) d[k] = 0.f;
        float cs[16];
        #pragma unroll 8
        for (int j = 0; j < 16; j++) {
            int c = wid + 8 * j;
            float w = __ldg(&wp1[c]);
            const float4* cp = (const float4*)(plane + ((size_t)c << 14));
            float4 v0 = cp[lane];
            float4 v1 = cp[lane + 32];
            d[0] = fmaf(w, v0.x, d[0]); d[1] = fmaf(w, v0.y, d[1]);
            d[2] = fmaf(w, v0.z, d[2]); d[3] = fmaf(w, v0.w, d[3]);
            d[4] = fmaf(w, v1.x, d[4]); d[5] = fmaf(w, v1.y, d[5]);
            d[6] = fmaf(w, v1.z, d[6]); d[7] = fmaf(w, v1.w, d[7]);
            cs[j] = ((v0.x + v0.y) + (v0.z + v0.w)) + ((v1.x + v1.y) + (v1.z + v1.w));
        }
        #pragma unroll
        for (int j = 0; j < 16; j++) cpart[wid][j][lane] = cs[j];
        ((float4*)&part[wid][lane * 4])[0]       = make_float4(d[0], d[1], d[2], d[3]);
        ((float4*)&part[wid][128 + lane * 4])[0] = make_float4(d[4], d[5], d[6], d[7]);
        __syncthreads();
        float dot = bp1[0];
        #pragma unroll
        for (int w = 0; w < 8; w++) dot += part[w][tid];
        int p = p0 + tid;
        int y = p >> 7, x = p & 127;
        int n  = ((y >> 3) << 4) | (x >> 3);
        int ij = ((y & 7) << 3) | (x & 7);
        g_pos1[((b << 8) | n) * 64 + ij] = dot;
        if (tid < 128) {                 // channel-sum reduce: thread owns (warp, j)
            int w = tid >> 4, j = tid & 15;
            float s = 0.f;
            #pragma unroll
            for (int l = 0; l < 32; l++) s += cpart[w][j][l];
            atomicAdd(&g_gaps[b * C1N + w + 8 * j], s);
        }
    } else {
        // ---- pos2: warp owns 8 channels x 256 pixels ----
        int bid = blockIdx.x - 256;
        int b = bid >> 8;
        int p0 = (bid & 255) << 8;
        const float* plane = x2 + (size_t)b * C2N * NPIX2 + p0;
        float d[8];
        #pragma unroll
        for (int k = 0; k < 8; k++) d[k] = 0.f;
        float cs[8];
        #pragma unroll
        for (int j = 0; j < 8; j++) {
            int c = wid + 8 * j;
            float w = __ldg(&wp2[c]);
            const float4* cp = (const float4*)(plane + ((size_t)c << 16));
            float4 v0 = cp[lane];
            float4 v1 = cp[lane + 32];
            d[0] = fmaf(w, v0.x, d[0]); d[1] = fmaf(w, v0.y, d[1]);
            d[2] = fmaf(w, v0.z, d[2]); d[3] = fmaf(w, v0.w, d[3]);
            d[4] = fmaf(w, v1.x, d[4]); d[5] = fmaf(w, v1.y, d[5]);
            d[6] = fmaf(w, v1.z, d[6]); d[7] = fmaf(w, v1.w, d[7]);
            cs[j] = ((v0.x + v0.y) + (v0.z + v0.w)) + ((v1.x + v1.y) + (v1.z + v1.w));
        }
        #pragma unroll
        for (int j = 0; j < 8; j++) cpart[wid][j][lane] = cs[j];
        ((float4*)&part[wid][lane * 4])[0]       = make_float4(d[0], d[1], d[2], d[3]);
        ((float4*)&part[wid][128 + lane * 4])[0] = make_float4(d[4], d[5], d[6], d[7]);
        __syncthreads();
        float dot = bp2[0];
        #pragma unroll
        for (int w = 0; w < 8; w++) dot += part[w][tid];
        int p = p0 + tid;
        int y = p >> 8, x = p & 255;
        int n  = ((y >> 4) << 4) | (x >> 4);
        int ij = ((y & 15) << 4) | (x & 15);
        g_pos2[((b << 8) | n) * 256 + ij] = dot;
        if (tid < 64) {
            int w = tid >> 3, j = tid & 7;
            float s = 0.f;
            #pragma unroll
            for (int l = 0; l < 32; l++) s += cpart[w][j][l];
            atomicAdd(&g_gaps[BATCH * C1N + b * C2N + w + 8 * j], s);
        }
    }
}

// ---- kernel 2: mlp -> cw softmax (redundant per CTA) -> prefused w3t/s3/t3 ----
__global__ void __launch_bounds__(256) k_w3(const float* __restrict__ wc1, const float* __restrict__ bc1,
                                            const float* __restrict__ wc2, const float* __restrict__ bc2,
                                            const float* __restrict__ wf,  const float* __restrict__ bf,
                                            const float* __restrict__ gamma, const float* __restrict__ beta) {
    __shared__ float s_m1[256], s_m2[256], s_cw[256];
    int t = threadIdx.x;
    int b = t >> 6, g = (t >> 3) & 7, o = t & 7;
    const float INV1 = 1.f / NPIX1, INV2 = 1.f / NPIX2;
    {
        float a = bc1[o];
        const float* gp = &g_gaps[b * C1N + g * 16];
        #pragma unroll
        for (int c = 0; c < 16; c++) a = fmaf(wc1[o * 16 + c] * INV1, gp[c], a);
        s_m1[t] = fmaxf(a, 0.f);
    }
    {
        float a = bc2[o];
        const float* gp = &g_gaps[BATCH * C1N + b * C2N + g * 8];
        #pragma unroll
        for (int c = 0; c < 8; c++) a = fmaf(wc2[o * 8 + c] * INV2, gp[c], a);
        s_m2[t] = fmaxf(a, 0.f);
    }
    __syncthreads();
    if (t < 32) {
        int bb = t >> 3, gg = t & 7;
        int base = bb * 64 + gg * 8;
        float nr = 0.f;
        #pragma unroll
        for (int j = 0; j < 8; j++) { float m = s_m2[base + j]; nr += m * m; }
        float lg[8]; float mx = -1e30f;
        #pragma unroll
        for (int j = 0; j < 8; j++) { lg[j] = s_m1[base + j] * nr; mx = fmaxf(mx, lg[j]); }
        float Z = 0.f;
        #pragma unroll
        for (int j = 0; j < 8; j++) { lg[j] = expf(lg[j] - mx); Z += lg[j]; }
        float iz = 1.f / Z;
        #pragma unroll
        for (int j = 0; j < 8; j++) s_cw[base + j] = lg[j] * iz;
    }
    __syncthreads();
    const float A = rsqrtf(1.f + 1e-5f);
    #pragma unroll
    for (int k = 0; k < 4; k++) {            // this CTA's 1024-elem slice of [b][c][o]
        int i = blockIdx.x * 1024 + k * 256 + t;
        int bb = i >> 12, co = i & 4095, cc = co >> 6, oo = co & 63;
        g_w3t[i] = gamma[oo] * A * wf[oo * 64 + cc] * s_cw[bb * 64 + cc];
    }
    if (blockIdx.x == 0 && t < 64) {
        float ws = 0.f;
        for (int c = 0; c < 64; c++) ws += wf[t * 64 + c];
        float Ao = gamma[t] * A;
        g_s3[t] = Ao * ws;
        g_t3[t] = Ao * bf[t] + beta[t];
    }
}

// ---- kernel 3: per-block spatial attention (lean registers, high occupancy) ----
__global__ void __launch_bounds__(256) k_spa(const float* __restrict__ wlin,
                                             const float* __restrict__ blin) {
    __shared__ __align__(16) float s_p1[64];
    __shared__ float s_x1t[256], s_p2[256], s_red[18];
    __shared__ float s_acc[8 * 256];
    const float LOG2E = 1.4426950408889634f;
    int tid = threadIdx.x, wid = tid >> 5, lane = tid & 31;
    int blk = blockIdx.x;                 // = b*256 + n
    if (tid < 64) s_p1[tid] = g_pos1[blk * 64 + tid];
    s_p2[tid] = g_pos2[blk * 256 + tid];
    __syncthreads();
    float acc_t = blin[tid];
    const float4* wr = (const float4*)(wlin + tid * 64);
    #pragma unroll
    for (int c4 = 0; c4 < 16; c4++) {
        float4 w = wr[c4];
        acc_t += w.x * s_p1[c4 * 4 + 0] + w.y * s_p1[c4 * 4 + 1]
               + w.z * s_p1[c4 * 4 + 2] + w.w * s_p1[c4 * 4 + 3];
    }
    acc_t *= LOG2E;                       // exp(z) = exp2(z*log2e)
    s_x1t[tid] = acc_t;
    float vmax = acc_t, vmin = acc_t;
    #pragma unroll
    for (int o = 16; o; o >>= 1) {
        vmax = fmaxf(vmax, __shfl_xor_sync(0xffffffffu, vmax, o));
        vmin = fminf(vmin, __shfl_xor_sync(0xffffffffu, vmin, o));
    }
    if (lane == 0) { s_red[wid] = vmax; s_red[8 + wid] = vmin; }
    __syncthreads();
    if (tid == 0) {
        float mx = s_red[0], mn = s_red[8];
        #pragma unroll
        for (int w = 1; w < 8; w++) { mx = fmaxf(mx, s_red[w]); mn = fminf(mn, s_red[8 + w]); }
        s_red[16] = mx; s_red[17] = mn;
    }
    __syncthreads();
    float xmax = s_red[16], xmin = s_red[17];

    float x1r[8];
    #pragma unroll
    for (int j = 0; j < 8; j++) x1r[j] = s_x1t[lane + 32 * j];

    float accl[8];
    #pragma unroll
    for (int j = 0; j < 8; j++) accl[j] = 0.f;

    #pragma unroll 2
    for (int q = wid; q < 256; q += 8) {
        float p = s_p2[q];
        float rm = (p >= 0.f) ? p * xmax : p * xmin;   // exact row max (log2 domain)
        float e[8]; float sum = 0.f;
        #pragma unroll
        for (int j = 0; j < 8; j++) {
            float v = ex2f(fmaf(p, x1r[j], -rm));      // single MUFU.EX2
            e[j] = v; sum += v;
        }
        #pragma unroll
        for (int o = 16; o; o >>= 1) sum += __shfl_xor_sync(0xffffffffu, sum, o);
        float coef = __fdividef(p, sum);
        #pragma unroll
        for (int j = 0; j < 8; j++) accl[j] = fmaf(coef, e[j], accl[j]);
    }
    #pragma unroll
    for (int j = 0; j < 8; j++) s_acc[wid * 256 + lane + 32 * j] = accl[j];
    __syncthreads();
    float v = 0.f;
    #pragma unroll
    for (int w = 0; w < 8; w++) v += s_acc[w * 256 + tid];
    g_spa[blk * 256 + tid] = v;
}

// ---- kernel 4: fused conv; 4 outputs x 4 pixels / thread (high occupancy) ----
// grid = b*1024 + n*4 + q. CTA = 64 outputs x 64 pixels.
__global__ void __launch_bounds__(256) k_fuse(const float* __restrict__ x2,
                                              float* __restrict__ out) {
    __shared__ __align__(16) float s_wd[C2N * 128];  // [c][2o] duplicated weights (32KB)
    __shared__ float s_s3[64], s_t3[64];
    int tid = threadIdx.x;
    int blk = blockIdx.x;
    int b = blk >> 10;
    int n = (blk >> 2) & 255;
    int q = blk & 3;
    int og = tid >> 4;                   // 0..15: outputs [og*4, +4)
    int pg = tid & 15;                   // pixels pg*4 .. +3 within 64-px quarter
    int p0 = n * 256 + q * 64 + pg * 4;
    int obase = og * 4;

    // re-zero the gap accumulators for the next graph replay
    if (blk < 3) {
        int i = blk * 256 + tid;
        if (i < BATCH * C1N + BATCH * C2N) g_gaps[i] = 0.f;
    }

    {   // build duplicated weight tile: each float4 of g_w3t -> two float4 of dups
        const float4* gw = (const float4*)&g_w3t[b * 4096];
        #pragma unroll
        for (int k = 0; k < 4; k++) {
            int g = k * 256 + tid;        // float4 index: c = g>>4, o4 = g&15
            float4 w = gw[g];
            float* dst = &s_wd[(g >> 4) * 128 + (g & 15) * 8];
            ((float4*)dst)[0] = make_float4(w.x, w.x, w.y, w.y);
            ((float4*)dst)[1] = make_float4(w.z, w.z, w.w, w.w);
        }
        if (tid < 64) { s_s3[tid] = g_s3[tid]; s_t3[tid] = g_t3[tid]; }
    }
    __syncthreads();

    unsigned long long acc[8];           // [o(0..3)][pixel-pair(0..1)]
    #pragma unroll
    for (int j = 0; j < 8; j++) acc[j] = 0ull;

    const double2* xb = (const double2*)(x2 + (size_t)b * C2N * NPIX2 + p0);
    #pragma unroll 4
    for (int c = 0; c < 64; c++) {
        double2 xv = xb[(size_t)c << 14];            // 4 px = 2 packed pairs
        unsigned long long xp0 = __double_as_longlong(xv.x);
        unsigned long long xp1 = __double_as_longlong(xv.y);
        const double2* wd = (const double2*)&s_wd[c * 128 + obase * 2];
        double2 wv0 = wd[0], wv1 = wd[1];            // 4 dup weight-pairs
        unsigned long long w0 = __double_as_longlong(wv0.x);
        unsigned long long w1 = __double_as_longlong(wv0.y);
        unsigned long long w2 = __double_as_longlong(wv1.x);
        unsigned long long w3 = __double_as_longlong(wv1.y);
        asm("fma.rn.f32x2 %0, %1, %2, %0;" : "+l"(acc[0]) : "l"(w0), "l"(xp0));
        asm("fma.rn.f32x2 %0, %1, %2, %0;" : "+l"(acc[1]) : "l"(w0), "l"(xp1));
        asm("fma.rn.f32x2 %0, %1, %2, %0;" : "+l"(acc[2]) : "l"(w1), "l"(xp0));
        asm("fma.rn.f32x2 %0, %1, %2, %0;" : "+l"(acc[3]) : "l"(w1), "l"(xp1));
        asm("fma.rn.f32x2 %0, %1, %2, %0;" : "+l"(acc[4]) : "l"(w2), "l"(xp0));
        asm("fma.rn.f32x2 %0, %1, %2, %0;" : "+l"(acc[5]) : "l"(w2), "l"(xp1));
        asm("fma.rn.f32x2 %0, %1, %2, %0;" : "+l"(acc[6]) : "l"(w3), "l"(xp0));
        asm("fma.rn.f32x2 %0, %1, %2, %0;" : "+l"(acc[7]) : "l"(w3), "l"(xp1));
    }
    float4 sv = *(const float4*)&g_spa[(size_t)b * NPIX2 + p0];
    float svk[4] = {sv.x, sv.y, sv.z, sv.w};
    float* ob = out + (size_t)b * C2N * NPIX2 + p0;
    #pragma unroll
    for (int o = 0; o < 4; o++) {
        int oo = obase + o;
        float s3 = s_s3[oo], t3 = s_t3[oo];
        float v[4];
        asm("mov.b64 {%0, %1}, %2;" : "=f"(v[0]), "=f"(v[1]) : "l"(acc[2*o+0]));
        asm("mov.b64 {%0, %1}, %2;" : "=f"(v[2]), "=f"(v[3]) : "l"(acc[2*o+1]));
        float r0 = fmaxf(fmaf(s3, svk[0], v[0]) + t3, 0.f);
        float r1 = fmaxf(fmaf(s3, svk[1], v[1]) + t3, 0.f);
        float r2 = fmaxf(fmaf(s3, svk[2], v[2]) + t3, 0.f);
        float r3 = fmaxf(fmaf(s3, svk[3], v[3]) + t3, 0.f);
        ((float4*)(ob + ((size_t)oo << 16)))[0] = make_float4(r0, r1, r2, r3);
    }
}

extern "C" void kernel_launch(void* const* d_in, const int* in_sizes, int n_in,
                              void* d_out, int out_size) {
    const float* x1    = (const float*)d_in[0];
    const float* x2    = (const float*)d_in[1];
    const float* wc1   = (const float*)d_in[2];
    const float* bc1   = (const float*)d_in[3];
    const float* wc2   = (const float*)d_in[4];
    const float* bc2   = (const float*)d_in[5];
    const float* wp1   = (const float*)d_in[6];
    const float* bp1   = (const float*)d_in[7];
    const float* wp2   = (const float*)d_in[8];
    const float* bp2   = (const float*)d_in[9];
    const float* wlin  = (const float*)d_in[10];
    const float* blin  = (const float*)d_in[11];
    const float* wf    = (const float*)d_in[12];
    const float* bf    = (const float*)d_in[13];
    const float* gamma = (const float*)d_in[14];
    const float* beta  = (const float*)d_in[15];
    float* out = (float*)d_out;

    k_pos <<<256 + 1024, 256>>>(x1, wp1, bp1, x2, wp2, bp2);
    k_w3  <<<16, 256>>>(wc1, bc1, wc2, bc2, wf, bf, gamma, beta);
    k_spa <<<BATCH * NB, 256>>>(wlin, blin);
    k_fuse<<<BATCH * NB * 4, 256>>>(x2, out);
}

// round 15
// speedup vs baseline: 1.2971x; 1.2971x over previous
#include <cuda_runtime.h>
#include <cuda_bf16.h>
#include <cstdint>

#define BATCH 4
#define C1N 128
#define C2N 64
#define NPIX1 16384   // 128*128
#define NPIX2 65536   // 256*256
#define NB 256

// ---- scratch (device globals; zero-init at load; k_fuse re-zeroes g_gaps) ----
__device__ float g_gaps[BATCH * C1N + BATCH * C2N];
__device__ __align__(16) float g_pos1[BATCH * NB * 64];   // [b][n][ij]
__device__ __align__(16) float g_pos2[BATCH * NB * 256];  // [b][n][ij]
__device__ __align__(16) float g_spa [BATCH * NPIX2];     // [b][h=n][w=k]
__device__ __align__(16) char  g_wcat[BATCH * 32768];     // [b][m=64][k=256] bf16 (Wh,Wh,Wl,Wl)
__device__ __align__(16) float g_s3  [C2N];
__device__ __align__(16) float g_t3  [C2N];

__device__ __forceinline__ float ex2f(float x) {
    float r;
    asm("ex2.approx.ftz.f32 %0, %1;" : "=f"(r) : "f"(x));
    return r;
}
__device__ __forceinline__ void mma_bf16(float* d, const uint32_t* a, const uint32_t* b) {
    asm volatile(
        "mma.sync.aligned.m16n8k16.row.col.f32.bf16.bf16.f32 "
        "{%0,%1,%2,%3}, {%4,%5,%6,%7}, {%8,%9}, {%0,%1,%2,%3};"
        : "+f"(d[0]), "+f"(d[1]), "+f"(d[2]), "+f"(d[3])
        : "r"(a[0]), "r"(a[1]), "r"(a[2]), "r"(a[3]), "r"(b[0]), "r"(b[1]));
}

// ---- kernel 1: pos1 & pos2 + channel sums (unchanged) ----
__global__ void __launch_bounds__(256) k_pos(const float* __restrict__ x1,
                                             const float* __restrict__ wp1,
                                             const float* __restrict__ bp1,
                                             const float* __restrict__ x2,
                                             const float* __restrict__ wp2,
                                             const float* __restrict__ bp2) {
    __shared__ __align__(16) float part[8][256];
    __shared__ float cpart[8][16][33];
    int tid = threadIdx.x, wid = tid >> 5, lane = tid & 31;

    if (blockIdx.x < 256) {
        int bid = blockIdx.x;
        int b = bid >> 6;
        int p0 = (bid & 63) << 8;
        const float* plane = x1 + (size_t)b * C1N * NPIX1 + p0;
        float d[8];
        #pragma unroll
        for (int k = 0; k < 8; k++) d[k] = 0.f;
        float cs[16];
        #pragma unroll 8
        for (int j = 0; j < 16; j++) {
            int c = wid + 8 * j;
            float w = __ldg(&wp1[c]);
            const float4* cp = (const float4*)(plane + ((size_t)c << 14));
            float4 v0 = cp[lane];
            float4 v1 = cp[lane + 32];
            d[0] = fmaf(w, v0.x, d[0]); d[1] = fmaf(w, v0.y, d[1]);
            d[2] = fmaf(w, v0.z, d[2]); d[3] = fmaf(w, v0.w, d[3]);
            d[4] = fmaf(w, v1.x, d[4]); d[5] = fmaf(w, v1.y, d[5]);
            d[6] = fmaf(w, v1.z, d[6]); d[7] = fmaf(w, v1.w, d[7]);
            cs[j] = ((v0.x + v0.y) + (v0.z + v0.w)) + ((v1.x + v1.y) + (v1.z + v1.w));
        }
        #pragma unroll
        for (int j = 0; j < 16; j++) cpart[wid][j][lane] = cs[j];
        ((float4*)&part[wid][lane * 4])[0]       = make_float4(d[0], d[1], d[2], d[3]);
        ((float4*)&part[wid][128 + lane * 4])[0] = make_float4(d[4], d[5], d[6], d[7]);
        __syncthreads();
        float dot = bp1[0];
        #pragma unroll
        for (int w = 0; w < 8; w++) dot += part[w][tid];
        int p = p0 + tid;
        int y = p >> 7, x = p & 127;
        int n  = ((y >> 3) << 4) | (x >> 3);
        int ij = ((y & 7) << 3) | (x & 7);
        g_pos1[((b << 8) | n) * 64 + ij] = dot;
        if (tid < 128) {
            int w = tid >> 4, j = tid & 15;
            float s = 0.f;
            #pragma unroll
            for (int l = 0; l < 32; l++) s += cpart[w][j][l];
            atomicAdd(&g_gaps[b * C1N + w + 8 * j], s);
        }
    } else {
        int bid = blockIdx.x - 256;
        int b = bid >> 8;
        int p0 = (bid & 255) << 8;
        const float* plane = x2 + (size_t)b * C2N * NPIX2 + p0;
        float d[8];
        #pragma unroll
        for (int k = 0; k < 8; k++) d[k] = 0.f;
        float cs[8];
        #pragma unroll
        for (int j = 0; j < 8; j++) {
            int c = wid + 8 * j;
            float w = __ldg(&wp2[c]);
            const float4* cp = (const float4*)(plane + ((size_t)c << 16));
            float4 v0 = cp[lane];
            float4 v1 = cp[lane + 32];
            d[0] = fmaf(w, v0.x, d[0]); d[1] = fmaf(w, v0.y, d[1]);
            d[2] = fmaf(w, v0.z, d[2]); d[3] = fmaf(w, v0.w, d[3]);
            d[4] = fmaf(w, v1.x, d[4]); d[5] = fmaf(w, v1.y, d[5]);
            d[6] = fmaf(w, v1.z, d[6]); d[7] = fmaf(w, v1.w, d[7]);
            cs[j] = ((v0.x + v0.y) + (v0.z + v0.w)) + ((v1.x + v1.y) + (v1.z + v1.w));
        }
        #pragma unroll
        for (int j = 0; j < 8; j++) cpart[wid][j][lane] = cs[j];
        ((float4*)&part[wid][lane * 4])[0]       = make_float4(d[0], d[1], d[2], d[3]);
        ((float4*)&part[wid][128 + lane * 4])[0] = make_float4(d[4], d[5], d[6], d[7]);
        __syncthreads();
        float dot = bp2[0];
        #pragma unroll
        for (int w = 0; w < 8; w++) dot += part[w][tid];
        int p = p0 + tid;
        int y = p >> 8, x = p & 255;
        int n  = ((y >> 4) << 4) | (x >> 4);
        int ij = ((y & 15) << 4) | (x & 15);
        g_pos2[((b << 8) | n) * 256 + ij] = dot;
        if (tid < 64) {
            int w = tid >> 3, j = tid & 7;
            float s = 0.f;
            #pragma unroll
            for (int l = 0; l < 32; l++) s += cpart[w][j][l];
            atomicAdd(&g_gaps[BATCH * C1N + b * C2N + w + 8 * j], s);
        }
    }
}

// ---- kernel 2: mlp -> cw softmax -> A image (Wh,Wh,Wl,Wl per channel) + s3/t3 ----
__global__ void __launch_bounds__(256) k_w3(const float* __restrict__ wc1, const float* __restrict__ bc1,
                                            const float* __restrict__ wc2, const float* __restrict__ bc2,
                                            const float* __restrict__ wf,  const float* __restrict__ bf,
                                            const float* __restrict__ gamma, const float* __restrict__ beta) {
    __shared__ float s_m1[256], s_m2[256], s_cw[256];
    int t = threadIdx.x;
    int b = t >> 6, g = (t >> 3) & 7, o = t & 7;
    const float INV1 = 1.f / NPIX1, INV2 = 1.f / NPIX2;
    {
        float a = bc1[o];
        const float* gp = &g_gaps[b * C1N + g * 16];
        #pragma unroll
        for (int c = 0; c < 16; c++) a = fmaf(wc1[o * 16 + c] * INV1, gp[c], a);
        s_m1[t] = fmaxf(a, 0.f);
    }
    {
        float a = bc2[o];
        const float* gp = &g_gaps[BATCH * C1N + b * C2N + g * 8];
        #pragma unroll
        for (int c = 0; c < 8; c++) a = fmaf(wc2[o * 8 + c] * INV2, gp[c], a);
        s_m2[t] = fmaxf(a, 0.f);
    }
    __syncthreads();
    if (t < 32) {
        int bb = t >> 3, gg = t & 7;
        int base = bb * 64 + gg * 8;
        float nr = 0.f;
        #pragma unroll
        for (int j = 0; j < 8; j++) { float m = s_m2[base + j]; nr += m * m; }
        float lg[8]; float mx = -1e30f;
        #pragma unroll
        for (int j = 0; j < 8; j++) { lg[j] = s_m1[base + j] * nr; mx = fmaxf(mx, lg[j]); }
        float Z = 0.f;
        #pragma unroll
        for (int j = 0; j < 8; j++) { lg[j] = expf(lg[j] - mx); Z += lg[j]; }
        float iz = 1.f / Z;
        #pragma unroll
        for (int j = 0; j < 8; j++) s_cw[base + j] = lg[j] * iz;
    }
    __syncthreads();
    const float A = rsqrtf(1.f + 1e-5f);
    // A image: [b][m=64][k=256] bf16, cols 4c..4c+3 = (Wh, Wh, Wl, Wl)
    #pragma unroll
    for (int j = 0; j < 4; j++) {
        int e = blockIdx.x * 1024 + j * 256 + t;      // e in [0, 16384): (b, m, c)
        int b2 = e >> 12, mc = e & 4095, m = mc >> 6, c = mc & 63;
        float w = gamma[m] * A * wf[m * 64 + c] * s_cw[b2 * 64 + c];
        __nv_bfloat16 wh = __float2bfloat16(w);
        __nv_bfloat16 wl = __float2bfloat16(w - __bfloat162float(wh));
        uint32_t h = __bfloat16_as_ushort(wh), l = __bfloat16_as_ushort(wl);
        *(uint2*)(g_wcat + b2 * 32768 + m * 512 + c * 8) =
            make_uint2(h | (h << 16), l | (l << 16));
    }
    if (blockIdx.x == 0 && t < 64) {
        float ws = 0.f;
        for (int c = 0; c < 64; c++) ws += wf[t * 64 + c];
        float Ao = gamma[t] * A;
        g_s3[t] = Ao * ws;
        g_t3[t] = Ao * bf[t] + beta[t];
    }
}

// ---- kernel 3: per-block spatial attention (unchanged) ----
__global__ void __launch_bounds__(256) k_spa(const float* __restrict__ wlin,
                                             const float* __restrict__ blin) {
    __shared__ __align__(16) float s_p1[64];
    __shared__ float s_x1t[256], s_p2[256], s_red[18];
    __shared__ float s_acc[8 * 256];
    const float LOG2E = 1.4426950408889634f;
    int tid = threadIdx.x, wid = tid >> 5, lane = tid & 31;
    int blk = blockIdx.x;
    if (tid < 64) s_p1[tid] = g_pos1[blk * 64 + tid];
    s_p2[tid] = g_pos2[blk * 256 + tid];
    __syncthreads();
    float acc_t = blin[tid];
    const float4* wr = (const float4*)(wlin + tid * 64);
    #pragma unroll
    for (int c4 = 0; c4 < 16; c4++) {
        float4 w = wr[c4];
        acc_t += w.x * s_p1[c4 * 4 + 0] + w.y * s_p1[c4 * 4 + 1]
               + w.z * s_p1[c4 * 4 + 2] + w.w * s_p1[c4 * 4 + 3];
    }
    acc_t *= LOG2E;
    s_x1t[tid] = acc_t;
    float vmax = acc_t, vmin = acc_t;
    #pragma unroll
    for (int o = 16; o; o >>= 1) {
        vmax = fmaxf(vmax, __shfl_xor_sync(0xffffffffu, vmax, o));
        vmin = fminf(vmin, __shfl_xor_sync(0xffffffffu, vmin, o));
    }
    if (lane == 0) { s_red[wid] = vmax; s_red[8 + wid] = vmin; }
    __syncthreads();
    if (tid == 0) {
        float mx = s_red[0], mn = s_red[8];
        #pragma unroll
        for (int w = 1; w < 8; w++) { mx = fmaxf(mx, s_red[w]); mn = fminf(mn, s_red[8 + w]); }
        s_red[16] = mx; s_red[17] = mn;
    }
    __syncthreads();
    float xmax = s_red[16], xmin = s_red[17];

    float x1r[8];
    #pragma unroll
    for (int j = 0; j < 8; j++) x1r[j] = s_x1t[lane + 32 * j];
    float accl[8];
    #pragma unroll
    for (int j = 0; j < 8; j++) accl[j] = 0.f;

    #pragma unroll 2
    for (int q = wid; q < 256; q += 8) {
        float p = s_p2[q];
        float rm = (p >= 0.f) ? p * xmax : p * xmin;
        float e[8]; float sum = 0.f;
        #pragma unroll
        for (int j = 0; j < 8; j++) {
            float v = ex2f(fmaf(p, x1r[j], -rm));
            e[j] = v; sum += v;
        }
        #pragma unroll
        for (int o = 16; o; o >>= 1) sum += __shfl_xor_sync(0xffffffffu, sum, o);
        float coef = __fdividef(p, sum);
        #pragma unroll
        for (int j = 0; j < 8; j++) accl[j] = fmaf(coef, e[j], accl[j]);
    }
    #pragma unroll
    for (int j = 0; j < 8; j++) s_acc[wid * 256 + lane + 32 * j] = accl[j];
    __syncthreads();
    float v = 0.f;
    #pragma unroll
    for (int w = 0; w < 8; w++) v += s_acc[w * 256 + tid];
    g_spa[blk * 256 + tid] = v;
}

// ---- kernel 4: warp-MMA bf16 fused conv ----
// CTA = half row (128 px): D[o=64][p=128] = A[64][K=256] x B[128px][K=256]^T
// smem rows padded to 528B (132 words): frag LDS bank = 4r + c -> conflict-free.
#define A_OFF   0
#define B_OFF   33792     // 64*528
#define SPA_OFF 101376    // B_OFF + 128*528
#define S3_OFF  101888
#define T3_OFF  102144
#define FUSE_SMEM 102400

__global__ void __launch_bounds__(256) k_fuse(const float* __restrict__ x2,
                                              float* __restrict__ out) {
    extern __shared__ __align__(16) char smem[];
    int tid = threadIdx.x, wid = tid >> 5, lane = tid & 31;
    int blk = blockIdx.x;                  // b*512 + n*2 + half
    int b = blk >> 9;
    int p0 = (blk & 511) * 128;            // pixel base within batch plane

    if (blk < 3) {
        int i = blk * 256 + tid;
        if (i < BATCH * C1N + BATCH * C2N) g_gaps[i] = 0.f;
    }

    // A copy: g_wcat[b] (64 rows x 512B) -> smem rows of 528B
    {
        const float4* gw = (const float4*)(g_wcat + (size_t)b * 32768);
        #pragma unroll
        for (int i = 0; i < 8; i++) {
            int idx = i * 256 + tid;       // (m = idx>>5, f4 = idx&31)
            *(float4*)(smem + A_OFF + (idx >> 5) * 528 + (idx & 31) * 16) = gw[idx];
        }
    }
    // B fill: per (pixel p, channel c): 8B = (xh, xl, xh, xl)
    {
        const float4* xb = (const float4*)(x2 + (size_t)b * C2N * NPIX2 + p0);
        #pragma unroll
        for (int i = 0; i < 8; i++) {
            int idx = i * 256 + tid;       // c = idx>>5 (0..63), q4 = idx&31
            int c = idx >> 5, q4 = idx & 31;
            float4 v = xb[((size_t)c << 14) + q4];
            float vv[4] = {v.x, v.y, v.z, v.w};
            #pragma unroll
            for (int e = 0; e < 4; e++) {
                int p = q4 * 4 + e;
                float f = vv[e];
                __nv_bfloat16 xh = __float2bfloat16(f);
                __nv_bfloat16 xl = __float2bfloat16(f - __bfloat162float(xh));
                uint32_t w0 = (uint32_t)__bfloat16_as_ushort(xh)
                            | ((uint32_t)__bfloat16_as_ushort(xl) << 16);
                *(uint2*)(smem + B_OFF + p * 528 + c * 8) = make_uint2(w0, w0);
            }
        }
    }
    if (tid < 32)
        ((float4*)(smem + SPA_OFF))[tid] = ((const float4*)(g_spa + (size_t)b * NPIX2 + p0))[tid];
    if (tid < 64) {
        ((float*)(smem + S3_OFF))[tid] = g_s3[tid];
        ((float*)(smem + T3_OFF))[tid] = g_t3[tid];
    }
    __syncthreads();

    // ---- MMA mainloop: warp owns 16 px (cols), all 64 outputs (rows) ----
    int r = lane >> 2;                     // 0..7
    int cb = (lane & 3) * 4;               // byte offset of k-pair
    const char* Ab = smem + A_OFF + r * 528 + cb;
    const char* Bb = smem + B_OFF + (wid * 16 + r) * 528 + cb;

    float d[8][4];
    #pragma unroll
    for (int i = 0; i < 8; i++)
        #pragma unroll
        for (int j = 0; j < 4; j++) d[i][j] = 0.f;

    #pragma unroll 4
    for (int s = 0; s < 16; s++) {
        int ko = s * 32;                   // 16 bf16 per k-step = 32B
        uint32_t a[4][4];
        #pragma unroll
        for (int i = 0; i < 4; i++) {
            const char* base = Ab + i * (16 * 528) + ko;
            a[i][0] = *(const uint32_t*)(base);
            a[i][1] = *(const uint32_t*)(base + 8 * 528);
            a[i][2] = *(const uint32_t*)(base + 16);
            a[i][3] = *(const uint32_t*)(base + 8 * 528 + 16);
        }
        uint32_t bf[2][2];
        #pragma unroll
        for (int j = 0; j < 2; j++) {
            const char* bb = Bb + j * (8 * 528) + ko;
            bf[j][0] = *(const uint32_t*)(bb);
            bf[j][1] = *(const uint32_t*)(bb + 16);
        }
        #pragma unroll
        for (int i = 0; i < 4; i++)
            #pragma unroll
            for (int j = 0; j < 2; j++)
                mma_bf16(d[i * 2 + j], a[i], bf[j]);
    }

    // ---- epilogue: + s3[o]*spa[p] + t3[o], ReLU, STG.64 ----
    const float* sspa = (const float*)(smem + SPA_OFF);
    const float* ss3  = (const float*)(smem + S3_OFF);
    const float* st3  = (const float*)(smem + T3_OFF);
    float* obase = out + (size_t)b * C2N * NPIX2 + p0;
    #pragma unroll
    for (int i = 0; i < 4; i++) {
        #pragma unroll
        for (int j = 0; j < 2; j++) {
            float* dd = d[i * 2 + j];
            int o0 = 16 * i + r, o1 = o0 + 8;
            int pl = wid * 16 + 8 * j + (lane & 3) * 2;
            float sp0 = sspa[pl], sp1 = sspa[pl + 1];
            float2 r0, r1;
            r0.x = fmaxf(fmaf(ss3[o0], sp0, dd[0]) + st3[o0], 0.f);
            r0.y = fmaxf(fmaf(ss3[o0], sp1, dd[1]) + st3[o0], 0.f);
            r1.x = fmaxf(fmaf(ss3[o1], sp0, dd[2]) + st3[o1], 0.f);
            r1.y = fmaxf(fmaf(ss3[o1], sp1, dd[3]) + st3[o1], 0.f);
            *(float2*)(obase + (size_t)o0 * NPIX2 + pl) = r0;
            *(float2*)(obase + (size_t)o1 * NPIX2 + pl) = r1;
        }
    }
}

extern "C" void kernel_launch(void* const* d_in, const int* in_sizes, int n_in,
                              void* d_out, int out_size) {
    const float* x1    = (const float*)d_in[0];
    const float* x2    = (const float*)d_in[1];
    const float* wc1   = (const float*)d_in[2];
    const float* bc1   = (const float*)d_in[3];
    const float* wc2   = (const float*)d_in[4];
    const float* bc2   = (const float*)d_in[5];
    const float* wp1   = (const float*)d_in[6];
    const float* bp1   = (const float*)d_in[7];
    const float* wp2   = (const float*)d_in[8];
    const float* bp2   = (const float*)d_in[9];
    const float* wlin  = (const float*)d_in[10];
    const float* blin  = (const float*)d_in[11];
    const float* wf    = (const float*)d_in[12];
    const float* bf    = (const float*)d_in[13];
    const float* gamma = (const float*)d_in[14];
    const float* beta  = (const float*)d_in[15];
    float* out = (float*)d_out;

    cudaFuncSetAttribute(k_fuse, cudaFuncAttributeMaxDynamicSharedMemorySize, FUSE_SMEM);

    k_pos <<<256 + 1024, 256>>>(x1, wp1, bp1, x2, wp2, bp2);
    k_w3  <<<16, 256>>>(wc1, bc1, wc2, bc2, wf, bf, gamma, beta);
    k_spa <<<BATCH * NB, 256>>>(wlin, blin);
    k_fuse<<<BATCH * NB * 2, 256, FUSE_SMEM>>>(x2, out);
}

// round 16
// speedup vs baseline: 1.4244x; 1.0981x over previous
#include <cuda_runtime.h>
#include <cuda_bf16.h>
#include <cstdint>

#define BATCH 4
#define C1N 128
#define C2N 64
#define NPIX1 16384   // 128*128
#define NPIX2 65536   // 256*256
#define NB 256

// ---- scratch (device globals; zero-init at load; k_fuse re-zeroes g_gaps) ----
__device__ float g_gaps[BATCH * C1N + BATCH * C2N];
__device__ __align__(16) float g_pos1[BATCH * NB * 64];   // [b][n][ij]
__device__ __align__(16) float g_pos2[BATCH * NB * 256];  // [b][n][ij]
__device__ __align__(16) float g_spa [BATCH * NPIX2];     // [b][h=n][w=k]
__device__ __align__(16) char  g_wcat[BATCH * 32768];     // [b][m=64][k=256] bf16 (Wh,Wh,Wl,Wl)
__device__ __align__(16) float g_s3  [C2N];
__device__ __align__(16) float g_t3  [C2N];

__device__ __forceinline__ float ex2f(float x) {
    float r;
    asm("ex2.approx.ftz.f32 %0, %1;" : "=f"(r) : "f"(x));
    return r;
}
__device__ __forceinline__ uint32_t smem_u32(const void* p) {
    uint32_t a;
    asm("{ .reg .u64 t; cvta.to.shared.u64 t, %1; cvt.u32.u64 %0, t; }" : "=r"(a) : "l"(p));
    return a;
}
__device__ __forceinline__ void mma_bf16(float* d, const uint32_t* a, const uint32_t* b) {
    asm volatile(
        "mma.sync.aligned.m16n8k16.row.col.f32.bf16.bf16.f32 "
        "{%0,%1,%2,%3}, {%4,%5,%6,%7}, {%8,%9}, {%0,%1,%2,%3};"
        : "+f"(d[0]), "+f"(d[1]), "+f"(d[2]), "+f"(d[3])
        : "r"(a[0]), "r"(a[1]), "r"(a[2]), "r"(a[3]), "r"(b[0]), "r"(b[1]));
}
__device__ __forceinline__ void ldm_x4(uint32_t* r, uint32_t addr) {
    asm volatile("ldmatrix.sync.aligned.m8n8.x4.shared.b16 {%0,%1,%2,%3}, [%4];"
        : "=r"(r[0]), "=r"(r[1]), "=r"(r[2]), "=r"(r[3]) : "r"(addr));
}

// ---- kernel 1: pos1 & pos2 + channel sums (unchanged) ----
__global__ void __launch_bounds__(256) k_pos(const float* __restrict__ x1,
                                             const float* __restrict__ wp1,
                                             const float* __restrict__ bp1,
                                             const float* __restrict__ x2,
                                             const float* __restrict__ wp2,
                                             const float* __restrict__ bp2) {
    __shared__ __align__(16) float part[8][256];
    __shared__ float cpart[8][16][33];
    int tid = threadIdx.x, wid = tid >> 5, lane = tid & 31;

    if (blockIdx.x < 256) {
        int bid = blockIdx.x;
        int b = bid >> 6;
        int p0 = (bid & 63) << 8;
        const float* plane = x1 + (size_t)b * C1N * NPIX1 + p0;
        float d[8];
        #pragma unroll
        for (int k = 0; k < 8; k++) d[k] = 0.f;
        float cs[16];
        #pragma unroll 8
        for (int j = 0; j < 16; j++) {
            int c = wid + 8 * j;
            float w = __ldg(&wp1[c]);
            const float4* cp = (const float4*)(plane + ((size_t)c << 14));
            float4 v0 = cp[lane];
            float4 v1 = cp[lane + 32];
            d[0] = fmaf(w, v0.x, d[0]); d[1] = fmaf(w, v0.y, d[1]);
            d[2] = fmaf(w, v0.z, d[2]); d[3] = fmaf(w, v0.w, d[3]);
            d[4] = fmaf(w, v1.x, d[4]); d[5] = fmaf(w, v1.y, d[5]);
            d[6] = fmaf(w, v1.z, d[6]); d[7] = fmaf(w, v1.w, d[7]);
            cs[j] = ((v0.x + v0.y) + (v0.z + v0.w)) + ((v1.x + v1.y) + (v1.z + v1.w));
        }
        #pragma unroll
        for (int j = 0; j < 16; j++) cpart[wid][j][lane] = cs[j];
        ((float4*)&part[wid][lane * 4])[0]       = make_float4(d[0], d[1], d[2], d[3]);
        ((float4*)&part[wid][128 + lane * 4])[0] = make_float4(d[4], d[5], d[6], d[7]);
        __syncthreads();
        float dot = bp1[0];
        #pragma unroll
        for (int w = 0; w < 8; w++) dot += part[w][tid];
        int p = p0 + tid;
        int y = p >> 7, x = p & 127;
        int n  = ((y >> 3) << 4) | (x >> 3);
        int ij = ((y & 7) << 3) | (x & 7);
        g_pos1[((b << 8) | n) * 64 + ij] = dot;
        if (tid < 128) {
            int w = tid >> 4, j = tid & 15;
            float s = 0.f;
            #pragma unroll
            for (int l = 0; l < 32; l++) s += cpart[w][j][l];
            atomicAdd(&g_gaps[b * C1N + w + 8 * j], s);
        }
    } else {
        int bid = blockIdx.x - 256;
        int b = bid >> 8;
        int p0 = (bid & 255) << 8;
        const float* plane = x2 + (size_t)b * C2N * NPIX2 + p0;
        float d[8];
        #pragma unroll
        for (int k = 0; k < 8; k++) d[k] = 0.f;
        float cs[8];
        #pragma unroll
        for (int j = 0; j < 8; j++) {
            int c = wid + 8 * j;
            float w = __ldg(&wp2[c]);
            const float4* cp = (const float4*)(plane + ((size_t)c << 16));
            float4 v0 = cp[lane];
            float4 v1 = cp[lane + 32];
            d[0] = fmaf(w, v0.x, d[0]); d[1] = fmaf(w, v0.y, d[1]);
            d[2] = fmaf(w, v0.z, d[2]); d[3] = fmaf(w, v0.w, d[3]);
            d[4] = fmaf(w, v1.x, d[4]); d[5] = fmaf(w, v1.y, d[5]);
            d[6] = fmaf(w, v1.z, d[6]); d[7] = fmaf(w, v1.w, d[7]);
            cs[j] = ((v0.x + v0.y) + (v0.z + v0.w)) + ((v1.x + v1.y) + (v1.z + v1.w));
        }
        #pragma unroll
        for (int j = 0; j < 8; j++) cpart[wid][j][lane] = cs[j];
        ((float4*)&part[wid][lane * 4])[0]       = make_float4(d[0], d[1], d[2], d[3]);
        ((float4*)&part[wid][128 + lane * 4])[0] = make_float4(d[4], d[5], d[6], d[7]);
        __syncthreads();
        float dot = bp2[0];
        #pragma unroll
        for (int w = 0; w < 8; w++) dot += part[w][tid];
        int p = p0 + tid;
        int y = p >> 8, x = p & 255;
        int n  = ((y >> 4) << 4) | (x >> 4);
        int ij = ((y & 15) << 4) | (x & 15);
        g_pos2[((b << 8) | n) * 256 + ij] = dot;
        if (tid < 64) {
            int w = tid >> 3, j = tid & 7;
            float s = 0.f;
            #pragma unroll
            for (int l = 0; l < 32; l++) s += cpart[w][j][l];
            atomicAdd(&g_gaps[BATCH * C1N + b * C2N + w + 8 * j], s);
        }
    }
}

// ---- kernel 2: mlp -> cw softmax -> A image (Wh,Wh,Wl,Wl per channel) + s3/t3 ----
__global__ void __launch_bounds__(256) k_w3(const float* __restrict__ wc1, const float* __restrict__ bc1,
                                            const float* __restrict__ wc2, const float* __restrict__ bc2,
                                            const float* __restrict__ wf,  const float* __restrict__ bf,
                                            const float* __restrict__ gamma, const float* __restrict__ beta) {
    __shared__ float s_m1[256], s_m2[256], s_cw[256];
    int t = threadIdx.x;
    int b = t >> 6, g = (t >> 3) & 7, o = t & 7;
    const float INV1 = 1.f / NPIX1, INV2 = 1.f / NPIX2;
    {
        float a = bc1[o];
        const float* gp = &g_gaps[b * C1N + g * 16];
        #pragma unroll
        for (int c = 0; c < 16; c++) a = fmaf(wc1[o * 16 + c] * INV1, gp[c], a);
        s_m1[t] = fmaxf(a, 0.f);
    }
    {
        float a = bc2[o];
        const float* gp = &g_gaps[BATCH * C1N + b * C2N + g * 8];
        #pragma unroll
        for (int c = 0; c < 8; c++) a = fmaf(wc2[o * 8 + c] * INV2, gp[c], a);
        s_m2[t] = fmaxf(a, 0.f);
    }
    __syncthreads();
    if (t < 32) {
        int bb = t >> 3, gg = t & 7;
        int base = bb * 64 + gg * 8;
        float nr = 0.f;
        #pragma unroll
        for (int j = 0; j < 8; j++) { float m = s_m2[base + j]; nr += m * m; }
        float lg[8]; float mx = -1e30f;
        #pragma unroll
        for (int j = 0; j < 8; j++) { lg[j] = s_m1[base + j] * nr; mx = fmaxf(mx, lg[j]); }
        float Z = 0.f;
        #pragma unroll
        for (int j = 0; j < 8; j++) { lg[j] = expf(lg[j] - mx); Z += lg[j]; }
        float iz = 1.f / Z;
        #pragma unroll
        for (int j = 0; j < 8; j++) s_cw[base + j] = lg[j] * iz;
    }
    __syncthreads();
    const float A = rsqrtf(1.f + 1e-5f);
    // A image: [b][m=64][k=256] bf16, cols 4c..4c+3 = (Wh, Wh, Wl, Wl)
    #pragma unroll
    for (int j = 0; j < 4; j++) {
        int e = blockIdx.x * 1024 + j * 256 + t;      // e in [0, 16384): (b, m, c)
        int b2 = e >> 12, mc = e & 4095, m = mc >> 6, c = mc & 63;
        float w = gamma[m] * A * wf[m * 64 + c] * s_cw[b2 * 64 + c];
        __nv_bfloat16 wh = __float2bfloat16(w);
        __nv_bfloat16 wl = __float2bfloat16(w - __bfloat162float(wh));
        uint32_t h = __bfloat16_as_ushort(wh), l = __bfloat16_as_ushort(wl);
        *(uint2*)(g_wcat + b2 * 32768 + m * 512 + c * 8) =
            make_uint2(h | (h << 16), l | (l << 16));
    }
    if (blockIdx.x == 0 && t < 64) {
        float ws = 0.f;
        for (int c = 0; c < 64; c++) ws += wf[t * 64 + c];
        float Ao = gamma[t] * A;
        g_s3[t] = Ao * ws;
        g_t3[t] = Ao * bf[t] + beta[t];
    }
}

// ---- kernel 3: per-block spatial attention (unchanged) ----
__global__ void __launch_bounds__(256) k_spa(const float* __restrict__ wlin,
                                             const float* __restrict__ blin) {
    __shared__ __align__(16) float s_p1[64];
    __shared__ float s_x1t[256], s_p2[256], s_red[18];
    __shared__ float s_acc[8 * 256];
    const float LOG2E = 1.4426950408889634f;
    int tid = threadIdx.x, wid = tid >> 5, lane = tid & 31;
    int blk = blockIdx.x;
    if (tid < 64) s_p1[tid] = g_pos1[blk * 64 + tid];
    s_p2[tid] = g_pos2[blk * 256 + tid];
    __syncthreads();
    float acc_t = blin[tid];
    const float4* wr = (const float4*)(wlin + tid * 64);
    #pragma unroll
    for (int c4 = 0; c4 < 16; c4++) {
        float4 w = wr[c4];
        acc_t += w.x * s_p1[c4 * 4 + 0] + w.y * s_p1[c4 * 4 + 1]
               + w.z * s_p1[c4 * 4 + 2] + w.w * s_p1[c4 * 4 + 3];
    }
    acc_t *= LOG2E;
    s_x1t[tid] = acc_t;
    float vmax = acc_t, vmin = acc_t;
    #pragma unroll
    for (int o = 16; o; o >>= 1) {
        vmax = fmaxf(vmax, __shfl_xor_sync(0xffffffffu, vmax, o));
        vmin = fminf(vmin, __shfl_xor_sync(0xffffffffu, vmin, o));
    }
    if (lane == 0) { s_red[wid] = vmax; s_red[8 + wid] = vmin; }
    __syncthreads();
    if (tid == 0) {
        float mx = s_red[0], mn = s_red[8];
        #pragma unroll
        for (int w = 1; w < 8; w++) { mx = fmaxf(mx, s_red[w]); mn = fminf(mn, s_red[8 + w]); }
        s_red[16] = mx; s_red[17] = mn;
    }
    __syncthreads();
    float xmax = s_red[16], xmin = s_red[17];

    float x1r[8];
    #pragma unroll
    for (int j = 0; j < 8; j++) x1r[j] = s_x1t[lane + 32 * j];
    float accl[8];
    #pragma unroll
    for (int j = 0; j < 8; j++) accl[j] = 0.f;

    #pragma unroll 2
    for (int q = wid; q < 256; q += 8) {
        float p = s_p2[q];
        float rm = (p >= 0.f) ? p * xmax : p * xmin;
        float e[8]; float sum = 0.f;
        #pragma unroll
        for (int j = 0; j < 8; j++) {
            float v = ex2f(fmaf(p, x1r[j], -rm));
            e[j] = v; sum += v;
        }
        #pragma unroll
        for (int o = 16; o; o >>= 1) sum += __shfl_xor_sync(0xffffffffu, sum, o);
        float coef = __fdividef(p, sum);
        #pragma unroll
        for (int j = 0; j < 8; j++) accl[j] = fmaf(coef, e[j], accl[j]);
    }
    #pragma unroll
    for (int j = 0; j < 8; j++) s_acc[wid * 256 + lane + 32 * j] = accl[j];
    __syncthreads();
    float v = 0.f;
    #pragma unroll
    for (int w = 0; w < 8; w++) v += s_acc[w * 256 + tid];
    g_spa[blk * 256 + tid] = v;
}

// ---- kernel 4: warp-MMA bf16 fused conv with ldmatrix fragments ----
// CTA = half row (128 px): D[o=64][p=128] = A[64][K=256] x B[128px][K=256]^T
// smem rows padded to 528B (132 words): ldmatrix 8x16B reads hit all 32 banks once.
#define A_OFF   0
#define B_OFF   33792     // 64*528
#define SPA_OFF 101376    // B_OFF + 128*528
#define S3_OFF  101888
#define T3_OFF  102144
#define FUSE_SMEM 102400

__global__ void __launch_bounds__(256) k_fuse(const float* __restrict__ x2,
                                              float* __restrict__ out) {
    extern __shared__ __align__(16) char smem[];
    int tid = threadIdx.x, wid = tid >> 5, lane = tid & 31;
    int blk = blockIdx.x;                  // b*512 + n*2 + half
    int b = blk >> 9;
    int p0 = (blk & 511) * 128;            // pixel base within batch plane

    if (blk < 3) {
        int i = blk * 256 + tid;
        if (i < BATCH * C1N + BATCH * C2N) g_gaps[i] = 0.f;
    }

    // A copy: g_wcat[b] (64 rows x 512B) -> smem rows of 528B
    {
        const float4* gw = (const float4*)(g_wcat + (size_t)b * 32768);
        #pragma unroll
        for (int i = 0; i < 8; i++) {
            int idx = i * 256 + tid;       // (m = idx>>5, f4 = idx&31)
            *(float4*)(smem + A_OFF + (idx >> 5) * 528 + (idx & 31) * 16) = gw[idx];
        }
    }
    // B fill: channel pairs -> one 16B store per pixel (xh0,xl0,xh0,xl0,xh1,xl1,xh1,xl1)
    {
        const float4* xb = (const float4*)(x2 + (size_t)b * C2N * NPIX2 + p0);
        #pragma unroll
        for (int i = 0; i < 4; i++) {
            int idx = i * 256 + tid;       // c2 = idx>>5 (0..31), q4 = idx&31
            int c = (idx >> 5) * 2, q4 = idx & 31;
            float4 v0 = xb[((size_t)(c + 0) << 14) + q4];
            float4 v1 = xb[((size_t)(c + 1) << 14) + q4];
            float a0[4] = {v0.x, v0.y, v0.z, v0.w};
            float a1[4] = {v1.x, v1.y, v1.z, v1.w};
            #pragma unroll
            for (int e = 0; e < 4; e++) {
                int p = q4 * 4 + e;
                __nv_bfloat16 h0 = __float2bfloat16(a0[e]);
                __nv_bfloat16 l0 = __float2bfloat16(a0[e] - __bfloat162float(h0));
                __nv_bfloat16 h1 = __float2bfloat16(a1[e]);
                __nv_bfloat16 l1 = __float2bfloat16(a1[e] - __bfloat162float(h1));
                uint32_t w0 = (uint32_t)__bfloat16_as_ushort(h0)
                            | ((uint32_t)__bfloat16_as_ushort(l0) << 16);
                uint32_t w1 = (uint32_t)__bfloat16_as_ushort(h1)
                            | ((uint32_t)__bfloat16_as_ushort(l1) << 16);
                *(uint4*)(smem + B_OFF + p * 528 + c * 8) = make_uint4(w0, w0, w1, w1);
            }
        }
    }
    if (tid < 32)
        ((float4*)(smem + SPA_OFF))[tid] = ((const float4*)(g_spa + (size_t)b * NPIX2 + p0))[tid];
    if (tid < 64) {
        ((float*)(smem + S3_OFF))[tid] = g_s3[tid];
        ((float*)(smem + T3_OFF))[tid] = g_t3[tid];
    }
    __syncthreads();

    // ---- MMA mainloop: warp owns 16 px (cols), all 64 outputs (rows) ----
    uint32_t smb = smem_u32(smem);
    int r8 = lane & 7;
    // A ldmatrix.x4: matrices (m0-7,k0),(m8-15,k0),(m0-7,k+16B),(m8-15,k+16B)
    uint32_t aAddr = smb + A_OFF + (((lane >> 3) & 1) * 8 + r8) * 528 + (lane >> 4) * 16;
    // B ldmatrix.x4: matrices (n0-7,k0),(n0-7,k+16B),(n8-15,k0),(n8-15,k+16B)
    uint32_t bAddr = smb + B_OFF + (wid * 16 + (lane >> 4) * 8 + r8) * 528 + ((lane >> 3) & 1) * 16;

    float d[8][4];
    #pragma unroll
    for (int i = 0; i < 8; i++)
        #pragma unroll
        for (int j = 0; j < 4; j++) d[i][j] = 0.f;

    #pragma unroll 4
    for (int s = 0; s < 16; s++) {
        uint32_t ko = s * 32;              // 16 bf16 per k-step = 32B
        uint32_t a[4][4], bf4[4];
        #pragma unroll
        for (int i = 0; i < 4; i++) ldm_x4(a[i], aAddr + i * (16 * 528) + ko);
        ldm_x4(bf4, bAddr + ko);
        #pragma unroll
        for (int i = 0; i < 4; i++) {
            mma_bf16(d[i * 2 + 0], a[i], bf4 + 0);
            mma_bf16(d[i * 2 + 1], a[i], bf4 + 2);
        }
    }

    // ---- epilogue: + s3[o]*spa[p] + t3[o], ReLU, STG.64 ----
    const float* sspa = (const float*)(smem + SPA_OFF);
    const float* ss3  = (const float*)(smem + S3_OFF);
    const float* st3  = (const float*)(smem + T3_OFF);
    int r = lane >> 2;
    float* obase = out + (size_t)b * C2N * NPIX2 + p0;
    #pragma unroll
    for (int i = 0; i < 4; i++) {
        #pragma unroll
        for (int j = 0; j < 2; j++) {
            float* dd = d[i * 2 + j];
            int o0 = 16 * i + r, o1 = o0 + 8;
            int pl = wid * 16 + 8 * j + (lane & 3) * 2;
            float sp0 = sspa[pl], sp1 = sspa[pl + 1];
            float2 r0, r1;
            r0.x = fmaxf(fmaf(ss3[o0], sp0, dd[0]) + st3[o0], 0.f);
            r0.y = fmaxf(fmaf(ss3[o0], sp1, dd[1]) + st3[o0], 0.f);
            r1.x = fmaxf(fmaf(ss3[o1], sp0, dd[2]) + st3[o1], 0.f);
            r1.y = fmaxf(fmaf(ss3[o1], sp1, dd[3]) + st3[o1], 0.f);
            *(float2*)(obase + (size_t)o0 * NPIX2 + pl) = r0;
            *(float2*)(obase + (size_t)o1 * NPIX2 + pl) = r1;
        }
    }
}

extern "C" void kernel_launch(void* const* d_in, const int* in_sizes, int n_in,
                              void* d_out, int out_size) {
    const float* x1    = (const float*)d_in[0];
    const float* x2    = (const float*)d_in[1];
    const float* wc1   = (const float*)d_in[2];
    const float* bc1   = (const float*)d_in[3];
    const float* wc2   = (const float*)d_in[4];
    const float* bc2   = (const float*)d_in[5];
    const float* wp1   = (const float*)d_in[6];
    const float* bp1   = (const float*)d_in[7];
    const float* wp2   = (const float*)d_in[8];
    const float* bp2   = (const float*)d_in[9];
    const float* wlin  = (const float*)d_in[10];
    const float* blin  = (const float*)d_in[11];
    const float* wf    = (const float*)d_in[12];
    const float* bf    = (const float*)d_in[13];
    const float* gamma = (const float*)d_in[14];
    const float* beta  = (const float*)d_in[15];
    float* out = (float*)d_out;

    cudaFuncSetAttribute(k_fuse, cudaFuncAttributeMaxDynamicSharedMemorySize, FUSE_SMEM);

    k_pos <<<256 + 1024, 256>>>(x1, wp1, bp1, x2, wp2, bp2);
    k_w3  <<<16, 256>>>(wc1, bc1, wc2, bc2, wf, bf, gamma, beta);
    k_spa <<<BATCH * NB, 256>>>(wlin, blin);
    k_fuse<<<BATCH * NB * 2, 256, FUSE_SMEM>>>(x2, out);
}